// round 8
// baseline (speedup 1.0000x reference)
#include <cuda_runtime.h>
#include <math.h>

// ---------------------------------------------------------------------------
// Problem constants
// ---------------------------------------------------------------------------
#define BATCH   4096
#define NTOK    64          // window size 8x8
#define CDIM    96
#define NHEADS  3
#define HD      32          // head dim
#define K4      384         // 4*C
#define SCALE   0.17677669529663687f   // 32^-0.5

// ---------------------------------------------------------------------------
// Scratch (device globals: the sanctioned alloc-free workaround)
// ---------------------------------------------------------------------------
__device__ float g_Ys [(size_t)BATCH * NTOK * K4];    // state projections
__device__ float g_Ye [(size_t)BATCH * NTOK * K4];    // input projections
__device__ float g_Mcv[(size_t)BATCH * NTOK * CDIM];
__device__ float g_Msv[(size_t)BATCH * NTOK * CDIM];
__device__ float g_Mch[(size_t)BATCH * NTOK * CDIM];
__device__ float g_Msh[(size_t)BATCH * NTOK * CDIM];
__device__ float g_bias[4 * NHEADS * NTOK * NTOK];    // [tbl][h][64*64]

// ---------------------------------------------------------------------------
// Packed f32x2 helpers (sm_103a FFMA2/FADD2 path; full fp32 precision)
// ---------------------------------------------------------------------------
typedef unsigned long long u64;

__device__ __forceinline__ u64 pack2(float lo, float hi)
{
    u64 r;
    asm("mov.b64 %0, {%1, %2};" : "=l"(r)
        : "r"(__float_as_uint(lo)), "r"(__float_as_uint(hi)));
    return r;
}
__device__ __forceinline__ void unpack2(float& lo, float& hi, u64 v)
{
    unsigned a, b;
    asm("mov.b64 {%0, %1}, %2;" : "=r"(a), "=r"(b) : "l"(v));
    lo = __uint_as_float(a);
    hi = __uint_as_float(b);
}
__device__ __forceinline__ void fma2(u64& d, u64 a, u64 b)
{
    asm("fma.rn.f32x2 %0, %1, %2, %0;" : "+l"(d) : "l"(a), "l"(b));
}
__device__ __forceinline__ u64 add2(u64 a, u64 b)
{
    u64 r;
    asm("add.rn.f32x2 %0, %1, %2;" : "=l"(r) : "l"(a), "l"(b));
    return r;
}

// ---------------------------------------------------------------------------
// Fast exp on the FMA pipe (no MUFU). Valid for x in [-87, 0]; rel err ~2e-6.
// ---------------------------------------------------------------------------
__device__ __forceinline__ float fast_exp(float x)
{
    const float L2E   = 1.4426950408889634f;
    const float MAGIC = 12582912.0f;          // 1.5 * 2^23
    float y = x * L2E;
    float t = y + MAGIC;
    float f = y - (t - MAGIC);                // f in [-0.5, 0.5]
    int   i = __float_as_int(t) - 0x4B400000; // round(y)
    float p = 1.33335581e-3f;
    p = fmaf(p, f, 9.61804886e-3f);
    p = fmaf(p, f, 5.55041087e-2f);
    p = fmaf(p, f, 2.40226507e-1f);
    p = fmaf(p, f, 6.93147182e-1f);
    p = fmaf(p, f, 1.0f);
    return __int_as_float(__float_as_int(p) + (i << 23));
}

// ---------------------------------------------------------------------------
// cp.async helpers
// ---------------------------------------------------------------------------
__device__ __forceinline__ void cpa4(unsigned dst, const float* src)
{
    asm volatile("cp.async.ca.shared.global [%0], [%1], 4;"
                 :: "r"(dst), "l"(src));
}
__device__ __forceinline__ void cpa4z(unsigned dst, const float* src, int ok)
{
    asm volatile("cp.async.ca.shared.global [%0], [%1], 4, %2;"
                 :: "r"(dst), "l"(src), "r"(ok ? 4 : 0));
}
__device__ __forceinline__ void cpa_commit()
{
    asm volatile("cp.async.commit_group;");
}

// ---------------------------------------------------------------------------
// GEMM: C[M,Nn] = concat(A1,A2)[M,K] @ W[Nn,K]^T + bias[Nn]
// Tile 128x128, k-chunk 16, 256 threads, 8x8 micro-tile, FFMA2 inner loop,
// cp.async double-buffered smem pipeline (GMEM latency overlapped).
// ---------------------------------------------------------------------------
#define BM 128
#define BN 128
#define BKC 16
#define APAD 132   // 128 + 4

__global__ __launch_bounds__(256, 2)
void gemm_bias(const float* __restrict__ A1, const float* __restrict__ A2,
               int lda1, int lda2, int Ksplit, int K, int Nn,
               const float* __restrict__ W, const float* __restrict__ bias,
               float* __restrict__ Cout)
{
    __shared__ float As[2][BKC][APAD];
    __shared__ float Bs[2][BKC][APAD];

    const int t     = threadIdx.x;
    const int mBase = blockIdx.x * BM;
    const int nBase = blockIdx.y * BN;
    const int kk    = t & 15;     // 0..15 : k within chunk
    const int rrow  = t >> 4;     // 0..15
    const int tx    = t & 15;     // m micro-tile
    const int ty    = t >> 4;     // n micro-tile

    const unsigned sA = (unsigned)__cvta_generic_to_shared(&As[0][0][0]);
    const unsigned sB = (unsigned)__cvta_generic_to_shared(&Bs[0][0][0]);

    u64 acc[8][4];                // [m-row][col-pair]
    #pragma unroll
    for (int i = 0; i < 8; i++)
        #pragma unroll
        for (int j = 0; j < 4; j++) acc[i][j] = 0ull;

    // issue one k-chunk's copies into buffer `buf`
    auto issue = [&](int k0, int buf) {
        const float* A;
        int lda, kcol;
        if (k0 < Ksplit) { A = A1; lda = lda1; kcol = k0; }
        else             { A = A2; lda = lda2; kcol = k0 - Ksplit; }
        unsigned dA = sA + (unsigned)(((buf * BKC + kk) * APAD) * 4);
        unsigned dB = sB + (unsigned)(((buf * BKC + kk) * APAD) * 4);
        #pragma unroll
        for (int r = 0; r < 8; r++) {
            int m = rrow + r * 16;
            cpa4(dA + m * 4, &A[(size_t)(mBase + m) * lda + kcol + kk]);
        }
        #pragma unroll
        for (int r = 0; r < 8; r++) {
            int n = rrow + r * 16;
            int ok = (nBase + n < Nn);
            const float* src = &W[(size_t)(ok ? (nBase + n) : 0) * K + k0 + kk];
            cpa4z(dB + n * 4, src, ok);
        }
        cpa_commit();
    };

    const int NC = K / BKC;
    issue(0, 0);

    for (int c = 0; c < NC; c++) {
        const int buf = c & 1;
        if (c + 1 < NC) {
            issue((c + 1) * BKC, (c + 1) & 1);
            asm volatile("cp.async.wait_group 1;");
        } else {
            asm volatile("cp.async.wait_group 0;");
        }
        __syncthreads();

        const float (*Ab)[APAD] = As[buf];
        const float (*Bb)[APAD] = Bs[buf];
        #pragma unroll
        for (int q = 0; q < BKC; q++) {
            float4 a0 = *(const float4*)&Ab[q][tx * 4];
            float4 a1 = *(const float4*)&Ab[q][64 + tx * 4];
            ulonglong2 bb0 = *(const ulonglong2*)&Bb[q][ty * 4];
            ulonglong2 bb1 = *(const ulonglong2*)&Bb[q][64 + ty * 4];
            u64 bn2[4] = {bb0.x, bb0.y, bb1.x, bb1.y};
            float am[8] = {a0.x, a0.y, a0.z, a0.w, a1.x, a1.y, a1.z, a1.w};
            #pragma unroll
            for (int i = 0; i < 8; i++) {
                u64 am2 = pack2(am[i], am[i]);
                #pragma unroll
                for (int j = 0; j < 4; j++)
                    fma2(acc[i][j], am2, bn2[j]);
            }
        }
        __syncthreads();
    }

    // Epilogue: unpack pairs, add bias, float4 stores.
    #pragma unroll
    for (int ih = 0; ih < 2; ih++) {
        #pragma unroll
        for (int i = 0; i < 4; i++) {
            int row = mBase + ih * 64 + tx * 4 + i;
            #pragma unroll
            for (int jh = 0; jh < 2; jh++) {
                int col = nBase + jh * 64 + ty * 4;
                if (col < Nn) {
                    float4 bv = *(const float4*)&bias[col];
                    float x0, x1, x2, x3;
                    unpack2(x0, x1, acc[ih * 4 + i][jh * 2 + 0]);
                    unpack2(x2, x3, acc[ih * 4 + i][jh * 2 + 1]);
                    float4 r;
                    r.x = x0 + bv.x;
                    r.y = x1 + bv.y;
                    r.z = x2 + bv.z;
                    r.w = x3 + bv.w;
                    *(float4*)&Cout[(size_t)row * Nn + col] = r;
                }
            }
        }
    }
}

// ---------------------------------------------------------------------------
// Bias pre-gather: g_bias[tbl][h][i*64+j] = tbl[rel_idx[i*64+j] * 3 + h]
// ---------------------------------------------------------------------------
__global__ void bias_gather(const float* __restrict__ tcv,
                            const float* __restrict__ tsv,
                            const float* __restrict__ tch,
                            const float* __restrict__ tsh,
                            const int*   __restrict__ rel_idx)
{
    const int tbl = blockIdx.y;
    const int h   = blockIdx.z;
    const float* T = (tbl == 0) ? tcv : (tbl == 1) ? tsv : (tbl == 2) ? tch : tsh;
    int idx = blockIdx.x * 256 + threadIdx.x;
    g_bias[(size_t)(tbl * NHEADS + h) * (NTOK * NTOK) + idx] =
        T[rel_idx[idx] * NHEADS + h];
}

// ---------------------------------------------------------------------------
// Window attention. Grid (BATCH, NHEADS, 2). 128 threads, 4 warps.
//   z = 0: source = Ys  -> typeA = attn_cv (scale),  typeB = attn_sh (scale^2)
//   z = 1: source = Ye  -> typeA = attn_sv (1.0),    typeB = attn_ch (scale)
// Lane owns one query row; FFMA2 QK/PV, FADD2 tree reduction, pre-gathered
// bias streamed with coalesced float4 LDGs.
// ---------------------------------------------------------------------------
#define TP 36                                  // tile pitch (floats)
#define TSZ (NTOK * TP)                        // 2304 floats per tile
#define SP 65                                  // score/bias pitch
#define ATTN_SMEM ((4 * TSZ + 2 * NTOK * SP) * sizeof(float))   // 70144 B

__global__ __launch_bounds__(128)
void attn_kernel(const int* __restrict__ rel_idx /*unused, kept for ABI*/)
{
    extern __shared__ float sm[];
    float* tiles = sm;                 // [4][64][TP]
    float* biasS = sm + 4 * TSZ;       // [2][64][SP] : bias, then scores

    const int b = blockIdx.x;
    const int h = blockIdx.y;
    const int z = blockIdx.z;

    const float* Y    = z ? g_Ye : g_Ys;
    const float  sclA = z ? 1.0f  : SCALE;
    const float  sclB = z ? SCALE : SCALE * SCALE;
    float* outAp = z ? g_Msv : g_Mcv;
    float* outBp = z ? g_Mch : g_Msh;
    // table ids: 0=cv 1=sv 2=ch 3=sh ; A = z?sv:cv, B = z?ch:sh
    const float* bA = g_bias + (size_t)((z ? 1 : 0) * NHEADS + h) * (NTOK * NTOK);
    const float* bB = g_bias + (size_t)((z ? 2 : 3) * NHEADS + h) * (NTOK * NTOK);

    const int t    = threadIdx.x;
    const int lane = t & 31;
    const int warp = t >> 5;

    // ---- load 4 projection tiles [64][32] (cols j4*96 + h*32 + lane) ----
    #pragma unroll
    for (int j4 = 0; j4 < 4; j4++) {
        #pragma unroll
        for (int r = 0; r < 16; r++) {
            int i = warp * 16 + r;
            tiles[j4 * TSZ + i * TP + lane] =
                Y[(size_t)(b * NTOK + i) * K4 + j4 * CDIM + h * HD + lane];
        }
    }

    // ---- stream pre-gathered bias into score buffer (coalesced LDG.128) ----
    for (int idx4 = t * 4; idx4 < NTOK * NTOK; idx4 += 128 * 4) {
        float4 va = *(const float4*)(bA + idx4);
        float4 vb = *(const float4*)(bB + idx4);
        int i = idx4 >> 6, j = idx4 & 63;
        float* pa = biasS + i * SP + j;
        float* pb = biasS + NTOK * SP + i * SP + j;
        pa[0] = va.x; pa[1] = va.y; pa[2] = va.z; pa[3] = va.w;
        pb[0] = vb.x; pb[1] = vb.y; pb[2] = vb.z; pb[3] = vb.w;
    }
    __syncthreads();

    const int   type = warp >> 1;     // 0 = A, 1 = B
    const int   half = warp & 1;      // query-row half
    const int   row  = half * 32 + lane;
    const float scl  = type ? sclB : sclA;
    const float* Kt  = tiles;                 // j4 = 0 (keys)
    const float* Vt  = tiles + TSZ;           // j4 = 1 (values)
    const float* qp  = tiles + (2 + type) * TSZ + row * TP;
    float* St        = biasS + type * NTOK * SP + row * SP;   // my score row
    float* outP      = type ? outBp : outAp;

    // ---- q row into registers as 16 packed pairs ----
    u64 qr2[16];
    #pragma unroll
    for (int c = 0; c < 8; c++) {
        ulonglong2 v2 = *(const ulonglong2*)(qp + 4 * c);
        qr2[2 * c + 0] = v2.x;
        qr2[2 * c + 1] = v2.y;
    }

    // ---- scores: S[row][j] = scl * <q_row, k_j> + bias (pairwise dot) ----
    #pragma unroll 4
    for (int j = 0; j < NTOK; j++) {
        const float* kj = Kt + j * TP;
        u64 sA = 0ull, sB = 0ull, sC = 0ull, sD = 0ull;
        #pragma unroll
        for (int c = 0; c < 4; c++) {
            ulonglong2 k0 = *(const ulonglong2*)(kj + 8 * c);       // broadcast
            ulonglong2 k1 = *(const ulonglong2*)(kj + 8 * c + 4);
            fma2(sA, qr2[4 * c + 0], k0.x);
            fma2(sB, qr2[4 * c + 1], k0.y);
            fma2(sC, qr2[4 * c + 2], k1.x);
            fma2(sD, qr2[4 * c + 3], k1.y);
        }
        u64 sT = add2(add2(sA, sB), add2(sC, sD));
        float lo, hi;
        unpack2(lo, hi, sT);
        St[j] = fmaf(scl, lo + hi, St[j]);
    }

    // ---- softmax over my row (FMA-pipe exp; normalization deferred) ----
    float mx = -1e30f;
    #pragma unroll
    for (int j = 0; j < NTOK; j++) mx = fmaxf(mx, St[j]);
    float sum = 0.f;
    #pragma unroll
    for (int j = 0; j < NTOK; j++) {
        float e = fast_exp(St[j] - mx);
        St[j] = e;
        sum += e;
    }
    const float inv = 1.f / sum;

    // ---- out pairs: ou2[c] += p2 * v_pair, c = 16 pairs (32 dims) ----
    u64 ou2[16];
    #pragma unroll
    for (int c = 0; c < 16; c++) ou2[c] = 0ull;
    #pragma unroll 4
    for (int j = 0; j < NTOK; j++) {
        const float p = St[j];
        const u64 p2 = pack2(p, p);
        const float* vj = Vt + j * TP;
        #pragma unroll
        for (int c = 0; c < 8; c++) {
            ulonglong2 vv = *(const ulonglong2*)(vj + 4 * c);   // broadcast
            fma2(ou2[2 * c + 0], p2, vv.x);
            fma2(ou2[2 * c + 1], p2, vv.y);
        }
    }
    float* op = outP + (size_t)(b * NTOK + row) * CDIM + h * HD;
    #pragma unroll
    for (int c = 0; c < 8; c++) {
        float x0, x1, x2, x3;
        unpack2(x0, x1, ou2[2 * c + 0]);
        unpack2(x2, x3, ou2[2 * c + 1]);
        float4 r;
        r.x = x0 * inv; r.y = x1 * inv; r.z = x2 * inv; r.w = x3 * inv;
        *(float4*)(op + 4 * c) = r;
    }
}

// ---------------------------------------------------------------------------
// Launch
// ---------------------------------------------------------------------------
extern "C" void kernel_launch(void* const* d_in, const int* in_sizes, int n_in,
                              void* d_out, int out_size)
{
    const float* input_x = (const float*)d_in[0];
    const float* state_x = (const float*)d_in[1];
    const float* Ws      = (const float*)d_in[2];
    const float* bs      = (const float*)d_in[3];
    const float* We      = (const float*)d_in[4];
    const float* be      = (const float*)d_in[5];
    const float* tcv     = (const float*)d_in[6];
    const float* tsv     = (const float*)d_in[7];
    const float* tch     = (const float*)d_in[8];
    const float* tsh     = (const float*)d_in[9];
    const float* Wpv     = (const float*)d_in[10];
    const float* bpv     = (const float*)d_in[11];
    const float* Wph     = (const float*)d_in[12];
    const float* bph     = (const float*)d_in[13];
    const int*   rel_idx = (const int*)d_in[14];

    float* out   = (float*)d_out;
    float* state = out + (size_t)BATCH * NTOK * CDIM;

    float *pYs, *pYe, *pMcv, *pMsv, *pMch, *pMsh;
    cudaGetSymbolAddress((void**)&pYs,  g_Ys);
    cudaGetSymbolAddress((void**)&pYe,  g_Ye);
    cudaGetSymbolAddress((void**)&pMcv, g_Mcv);
    cudaGetSymbolAddress((void**)&pMsv, g_Msv);
    cudaGetSymbolAddress((void**)&pMch, g_Mch);
    cudaGetSymbolAddress((void**)&pMsh, g_Msh);

    cudaFuncSetAttribute(attn_kernel,
                         cudaFuncAttributeMaxDynamicSharedMemorySize,
                         (int)ATTN_SMEM);

    const int M = BATCH * NTOK;          // 262144

    // Bias pre-gather (tiny; overlaps nothing it depends on)
    {
        dim3 grid(NTOK * NTOK / 256, 4, NHEADS);
        bias_gather<<<grid, 256>>>(tcv, tsv, tch, tsh, rel_idx);
    }

    // Stage 1: projections  Y = X @ W^T + b   -> [M, 384]
    {
        dim3 grid(M / BM, K4 / BN);      // (2048, 3)
        gemm_bias<<<grid, 256>>>(state_x, state_x, CDIM, CDIM, CDIM, CDIM, K4,
                                 Ws, bs, pYs);
        gemm_bias<<<grid, 256>>>(input_x, input_x, CDIM, CDIM, CDIM, CDIM, K4,
                                 We, be, pYe);
    }

    // Stage 2: 4 window attentions per (b, h)
    {
        dim3 grid(BATCH, NHEADS, 2);
        attn_kernel<<<grid, 128, ATTN_SMEM>>>(rel_idx);
    }

    // Stage 3: output projections on concatenated merges
    {
        dim3 grid(M / BM, (CDIM + BN - 1) / BN);   // (2048, 1)
        gemm_bias<<<grid, 256>>>(pMcv, pMsv, CDIM, CDIM, CDIM, 2 * CDIM, CDIM,
                                 Wpv, bpv, out);
        gemm_bias<<<grid, 256>>>(pMch, pMsh, CDIM, CDIM, CDIM, 2 * CDIM, CDIM,
                                 Wph, bph, state);
    }
}

// round 9
// speedup vs baseline: 1.0411x; 1.0411x over previous
#include <cuda_runtime.h>
#include <math.h>

// ---------------------------------------------------------------------------
// Problem constants
// ---------------------------------------------------------------------------
#define BATCH   4096
#define NTOK    64          // window size 8x8
#define CDIM    96
#define NHEADS  3
#define HD      32          // head dim
#define K4      384         // 4*C
#define MTOK    (BATCH * NTOK)               // 262144 tokens
#define SCALE   0.17677669529663687f   // 32^-0.5

// ---------------------------------------------------------------------------
// Scratch (device globals: the sanctioned alloc-free workaround)
// ---------------------------------------------------------------------------
__device__ float g_XsT[(size_t)CDIM * MTOK];          // state_x transposed
__device__ float g_XeT[(size_t)CDIM * MTOK];          // input_x transposed
__device__ float g_WsT[CDIM * K4];                    // Ws^T  [96][384]
__device__ float g_WeT[CDIM * K4];                    // We^T  [96][384]
__device__ float g_WpvT[2 * CDIM * CDIM];             // Wpv^T [192][96]
__device__ float g_WphT[2 * CDIM * CDIM];             // Wph^T [192][96]
__device__ float g_Ys [(size_t)MTOK * K4];            // state projections
__device__ float g_Ye [(size_t)MTOK * K4];            // input projections
__device__ float g_MvT[(size_t)2 * CDIM * MTOK];      // [cv | sv] transposed
__device__ float g_MhT[(size_t)2 * CDIM * MTOK];      // [ch | sh] transposed
__device__ float g_bias[4 * NHEADS * NTOK * NTOK];    // [tbl][h][64*64]

// ---------------------------------------------------------------------------
// Packed f32x2 helpers (sm_103a FFMA2/FADD2 path; full fp32 precision)
// ---------------------------------------------------------------------------
typedef unsigned long long u64;

__device__ __forceinline__ u64 pack2(float lo, float hi)
{
    u64 r;
    asm("mov.b64 %0, {%1, %2};" : "=l"(r)
        : "r"(__float_as_uint(lo)), "r"(__float_as_uint(hi)));
    return r;
}
__device__ __forceinline__ void unpack2(float& lo, float& hi, u64 v)
{
    unsigned a, b;
    asm("mov.b64 {%0, %1}, %2;" : "=r"(a), "=r"(b) : "l"(v));
    lo = __uint_as_float(a);
    hi = __uint_as_float(b);
}
__device__ __forceinline__ void fma2(u64& d, u64 a, u64 b)
{
    asm("fma.rn.f32x2 %0, %1, %2, %0;" : "+l"(d) : "l"(a), "l"(b));
}
__device__ __forceinline__ u64 add2(u64 a, u64 b)
{
    u64 r;
    asm("add.rn.f32x2 %0, %1, %2;" : "=l"(r) : "l"(a), "l"(b));
    return r;
}

// ---------------------------------------------------------------------------
// Fast exp on the FMA pipe (no MUFU). Valid for x in [-87, 0]; rel err ~2e-6.
// ---------------------------------------------------------------------------
__device__ __forceinline__ float fast_exp(float x)
{
    const float L2E   = 1.4426950408889634f;
    const float MAGIC = 12582912.0f;          // 1.5 * 2^23
    float y = x * L2E;
    float t = y + MAGIC;
    float f = y - (t - MAGIC);                // f in [-0.5, 0.5]
    int   i = __float_as_int(t) - 0x4B400000; // round(y)
    float p = 1.33335581e-3f;
    p = fmaf(p, f, 9.61804886e-3f);
    p = fmaf(p, f, 5.55041087e-2f);
    p = fmaf(p, f, 2.40226507e-1f);
    p = fmaf(p, f, 6.93147182e-1f);
    p = fmaf(p, f, 1.0f);
    return __int_as_float(__float_as_int(p) + (i << 23));
}

// ---------------------------------------------------------------------------
// cp.async helpers (16-byte)
// ---------------------------------------------------------------------------
__device__ __forceinline__ void cpa16(unsigned dst, const float* src)
{
    asm volatile("cp.async.ca.shared.global [%0], [%1], 16;"
                 :: "r"(dst), "l"(src));
}
__device__ __forceinline__ void cpa16z(unsigned dst, const float* src, int ok)
{
    asm volatile("cp.async.ca.shared.global [%0], [%1], 16, %2;"
                 :: "r"(dst), "l"(src), "r"(ok ? 16 : 0));
}
__device__ __forceinline__ void cpa_commit()
{
    asm volatile("cp.async.commit_group;");
}

// ---------------------------------------------------------------------------
// Transposes
// ---------------------------------------------------------------------------
__global__ __launch_bounds__(256)
void transpose_x(const float* __restrict__ X, float* __restrict__ Xt)
{
    __shared__ float tile[32][33];
    const int m0 = blockIdx.x * 32;
    const int k0 = blockIdx.y * 32;
    const int lx = threadIdx.x & 31;
    const int ly = threadIdx.x >> 5;     // 0..7
    #pragma unroll
    for (int i = 0; i < 4; i++)
        tile[ly + 8 * i][lx] = X[(size_t)(m0 + ly + 8 * i) * CDIM + k0 + lx];
    __syncthreads();
    #pragma unroll
    for (int i = 0; i < 4; i++)
        Xt[(size_t)(k0 + ly + 8 * i) * MTOK + m0 + lx] = tile[lx][ly + 8 * i];
}

__global__ void transpose_w(const float* __restrict__ W, float* __restrict__ Wt,
                            int Nr, int Kc)
{
    int idx = blockIdx.x * 256 + threadIdx.x;
    if (idx < Nr * Kc) {
        int n = idx / Kc, k = idx % Kc;
        Wt[(size_t)k * Nr + n] = W[idx];
    }
}

// ---------------------------------------------------------------------------
// GEMM (k-major inputs): C[M,Nn] = At[K,M]^T @ Wt[K,Nn] + bias[Nn]
// Tile 128x128, k-chunk 16, 256 threads, 8x8 micro-tile, FFMA2 inner loop,
// double-buffered 16B cp.async pipeline. C written row-major.
// ---------------------------------------------------------------------------
#define BM 128
#define BN 128
#define BKC 16
#define APAD 132   // 128 + 4 (132*4 = 528 B, multiple of 16)

__global__ __launch_bounds__(256, 2)
void gemm_t(const float* __restrict__ At, const float* __restrict__ Wt,
            const float* __restrict__ bias, float* __restrict__ Cout,
            int K, int Nn)
{
    __shared__ float As[2][BKC][APAD];
    __shared__ float Bs[2][BKC][APAD];

    const int t     = threadIdx.x;
    const int mBase = blockIdx.x * BM;
    const int nBase = blockIdx.y * BN;
    const int kk    = t & 15;     // k within chunk
    const int rr    = t >> 4;     // 0..15
    const int tx    = t & 15;     // m micro-tile
    const int ty    = t >> 4;     // n micro-tile

    const unsigned sA = (unsigned)__cvta_generic_to_shared(&As[0][0][0]);
    const unsigned sB = (unsigned)__cvta_generic_to_shared(&Bs[0][0][0]);

    u64 acc[8][4];
    #pragma unroll
    for (int i = 0; i < 8; i++)
        #pragma unroll
        for (int j = 0; j < 4; j++) acc[i][j] = 0ull;

    auto issue = [&](int k0, int buf) {
        const float* aRow = At + (size_t)(k0 + kk) * MTOK + mBase;
        const float* bRow = Wt + (size_t)(k0 + kk) * Nn + nBase;
        unsigned dA = sA + (unsigned)(((buf * BKC + kk) * APAD) * 4);
        unsigned dB = sB + (unsigned)(((buf * BKC + kk) * APAD) * 4);
        #pragma unroll
        for (int r = 0; r < 2; r++) {
            int g = rr * 4 + 64 * r;              // 16B group start
            cpa16(dA + g * 4, aRow + g);
            cpa16z(dB + g * 4, bRow + g, nBase + g < Nn);
        }
        cpa_commit();
    };

    const int NC = K / BKC;
    issue(0, 0);

    for (int c = 0; c < NC; c++) {
        const int buf = c & 1;
        if (c + 1 < NC) {
            issue((c + 1) * BKC, (c + 1) & 1);
            asm volatile("cp.async.wait_group 1;");
        } else {
            asm volatile("cp.async.wait_group 0;");
        }
        __syncthreads();

        const float (*Ab)[APAD] = As[buf];
        const float (*Bb)[APAD] = Bs[buf];
        #pragma unroll
        for (int q = 0; q < BKC; q++) {
            float4 a0 = *(const float4*)&Ab[q][tx * 4];
            float4 a1 = *(const float4*)&Ab[q][64 + tx * 4];
            ulonglong2 bb0 = *(const ulonglong2*)&Bb[q][ty * 4];
            ulonglong2 bb1 = *(const ulonglong2*)&Bb[q][64 + ty * 4];
            u64 bn2[4] = {bb0.x, bb0.y, bb1.x, bb1.y};
            float am[8] = {a0.x, a0.y, a0.z, a0.w, a1.x, a1.y, a1.z, a1.w};
            #pragma unroll
            for (int i = 0; i < 8; i++) {
                u64 am2 = pack2(am[i], am[i]);
                #pragma unroll
                for (int j = 0; j < 4; j++)
                    fma2(acc[i][j], am2, bn2[j]);
            }
        }
        __syncthreads();
    }

    // Epilogue: unpack pairs, add bias, float4 stores (row-major C).
    #pragma unroll
    for (int ih = 0; ih < 2; ih++) {
        #pragma unroll
        for (int i = 0; i < 4; i++) {
            int row = mBase + ih * 64 + tx * 4 + i;
            #pragma unroll
            for (int jh = 0; jh < 2; jh++) {
                int col = nBase + jh * 64 + ty * 4;
                if (col < Nn) {
                    float4 bv = *(const float4*)&bias[col];
                    float x0, x1, x2, x3;
                    unpack2(x0, x1, acc[ih * 4 + i][jh * 2 + 0]);
                    unpack2(x2, x3, acc[ih * 4 + i][jh * 2 + 1]);
                    float4 r;
                    r.x = x0 + bv.x;
                    r.y = x1 + bv.y;
                    r.z = x2 + bv.z;
                    r.w = x3 + bv.w;
                    *(float4*)&Cout[(size_t)row * Nn + col] = r;
                }
            }
        }
    }
}

// ---------------------------------------------------------------------------
// Bias pre-gather: g_bias[tbl][h][i*64+j] = tbl[rel_idx[i*64+j] * 3 + h]
// ---------------------------------------------------------------------------
__global__ void bias_gather(const float* __restrict__ tcv,
                            const float* __restrict__ tsv,
                            const float* __restrict__ tch,
                            const float* __restrict__ tsh,
                            const int*   __restrict__ rel_idx)
{
    const int tbl = blockIdx.y;
    const int h   = blockIdx.z;
    const float* T = (tbl == 0) ? tcv : (tbl == 1) ? tsv : (tbl == 2) ? tch : tsh;
    int idx = blockIdx.x * 256 + threadIdx.x;
    g_bias[(size_t)(tbl * NHEADS + h) * (NTOK * NTOK) + idx] =
        T[rel_idx[idx] * NHEADS + h];
}

// ---------------------------------------------------------------------------
// Window attention. Grid (BATCH, NHEADS, 2). 128 threads, 4 warps.
//   z = 0: source = Ys  -> typeA = attn_cv (scale),  typeB = attn_sh (scale^2)
//   z = 1: source = Ye  -> typeA = attn_sv (1.0),    typeB = attn_ch (scale)
// Lane owns one query row; FFMA2 QK/PV, FADD2 tree reduction.
// Outputs written TRANSPOSED (dim-major) into g_MvT / g_MhT: for a fixed dim,
// lanes hold consecutive tokens -> coalesced STG.32.
// ---------------------------------------------------------------------------
#define TP 36                                  // tile pitch (floats)
#define TSZ (NTOK * TP)                        // 2304 floats per tile
#define SP 65                                  // score/bias pitch
#define ATTN_SMEM ((4 * TSZ + 2 * NTOK * SP) * sizeof(float))   // 70144 B

__global__ __launch_bounds__(128)
void attn_kernel()
{
    extern __shared__ float sm[];
    float* tiles = sm;                 // [4][64][TP]
    float* biasS = sm + 4 * TSZ;       // [2][64][SP] : bias, then scores

    const int b = blockIdx.x;
    const int h = blockIdx.y;
    const int z = blockIdx.z;

    const float* Y    = z ? g_Ye : g_Ys;
    const float  sclA = z ? 1.0f  : SCALE;
    const float  sclB = z ? SCALE : SCALE * SCALE;
    // transposed output row bases:
    //   A: z0 = cv -> MvT rows [0,96) ; z1 = sv -> MvT rows [96,192)
    //   B: z0 = sh -> MhT rows [96,192) ; z1 = ch -> MhT rows [0,96)
    float* outA = g_MvT + (size_t)((z ? CDIM : 0) + h * HD) * MTOK;
    float* outB = g_MhT + (size_t)((z ? 0 : CDIM) + h * HD) * MTOK;
    const float* bA = g_bias + (size_t)((z ? 1 : 0) * NHEADS + h) * (NTOK * NTOK);
    const float* bB = g_bias + (size_t)((z ? 2 : 3) * NHEADS + h) * (NTOK * NTOK);

    const int t    = threadIdx.x;
    const int lane = t & 31;
    const int warp = t >> 5;

    // ---- load 4 projection tiles [64][32] (cols j4*96 + h*32 + lane) ----
    #pragma unroll
    for (int j4 = 0; j4 < 4; j4++) {
        #pragma unroll
        for (int r = 0; r < 16; r++) {
            int i = warp * 16 + r;
            tiles[j4 * TSZ + i * TP + lane] =
                Y[(size_t)(b * NTOK + i) * K4 + j4 * CDIM + h * HD + lane];
        }
    }

    // ---- stream pre-gathered bias into score buffer (coalesced LDG.128) ----
    for (int idx4 = t * 4; idx4 < NTOK * NTOK; idx4 += 128 * 4) {
        float4 va = *(const float4*)(bA + idx4);
        float4 vb = *(const float4*)(bB + idx4);
        int i = idx4 >> 6, j = idx4 & 63;
        float* pa = biasS + i * SP + j;
        float* pb = biasS + NTOK * SP + i * SP + j;
        pa[0] = va.x; pa[1] = va.y; pa[2] = va.z; pa[3] = va.w;
        pb[0] = vb.x; pb[1] = vb.y; pb[2] = vb.z; pb[3] = vb.w;
    }
    __syncthreads();

    const int   type = warp >> 1;     // 0 = A, 1 = B
    const int   half = warp & 1;      // query-row half
    const int   row  = half * 32 + lane;
    const float scl  = type ? sclB : sclA;
    const float* Kt  = tiles;                 // j4 = 0 (keys)
    const float* Vt  = tiles + TSZ;           // j4 = 1 (values)
    const float* qp  = tiles + (2 + type) * TSZ + row * TP;
    float* St        = biasS + type * NTOK * SP + row * SP;   // my score row
    float* outP      = type ? outB : outA;

    // ---- q row into registers as 16 packed pairs ----
    u64 qr2[16];
    #pragma unroll
    for (int c = 0; c < 8; c++) {
        ulonglong2 v2 = *(const ulonglong2*)(qp + 4 * c);
        qr2[2 * c + 0] = v2.x;
        qr2[2 * c + 1] = v2.y;
    }

    // ---- scores: S[row][j] = scl * <q_row, k_j> + bias (pairwise dot) ----
    #pragma unroll 4
    for (int j = 0; j < NTOK; j++) {
        const float* kj = Kt + j * TP;
        u64 sA = 0ull, sB = 0ull, sC = 0ull, sD = 0ull;
        #pragma unroll
        for (int c = 0; c < 4; c++) {
            ulonglong2 k0 = *(const ulonglong2*)(kj + 8 * c);       // broadcast
            ulonglong2 k1 = *(const ulonglong2*)(kj + 8 * c + 4);
            fma2(sA, qr2[4 * c + 0], k0.x);
            fma2(sB, qr2[4 * c + 1], k0.y);
            fma2(sC, qr2[4 * c + 2], k1.x);
            fma2(sD, qr2[4 * c + 3], k1.y);
        }
        u64 sT = add2(add2(sA, sB), add2(sC, sD));
        float lo, hi;
        unpack2(lo, hi, sT);
        St[j] = fmaf(scl, lo + hi, St[j]);
    }

    // ---- softmax over my row (FMA-pipe exp; normalization deferred) ----
    float mx = -1e30f;
    #pragma unroll
    for (int j = 0; j < NTOK; j++) mx = fmaxf(mx, St[j]);
    float sum = 0.f;
    #pragma unroll
    for (int j = 0; j < NTOK; j++) {
        float e = fast_exp(St[j] - mx);
        St[j] = e;
        sum += e;
    }
    const float inv = 1.f / sum;

    // ---- out pairs: ou2[c] += p2 * v_pair, c = 16 pairs (32 dims) ----
    u64 ou2[16];
    #pragma unroll
    for (int c = 0; c < 16; c++) ou2[c] = 0ull;
    #pragma unroll 4
    for (int j = 0; j < NTOK; j++) {
        const float p = St[j];
        const u64 p2 = pack2(p, p);
        const float* vj = Vt + j * TP;
        #pragma unroll
        for (int c = 0; c < 8; c++) {
            ulonglong2 vv = *(const ulonglong2*)(vj + 4 * c);   // broadcast
            fma2(ou2[2 * c + 0], p2, vv.x);
            fma2(ou2[2 * c + 1], p2, vv.y);
        }
    }

    // ---- transposed stores: dim-major, lanes = consecutive tokens ----
    float* op = outP + (size_t)b * NTOK + row;
    #pragma unroll
    for (int c = 0; c < 16; c++) {
        float x0, x1;
        unpack2(x0, x1, ou2[c]);
        op[(size_t)(2 * c + 0) * MTOK] = x0 * inv;
        op[(size_t)(2 * c + 1) * MTOK] = x1 * inv;
    }
}

// ---------------------------------------------------------------------------
// Launch
// ---------------------------------------------------------------------------
extern "C" void kernel_launch(void* const* d_in, const int* in_sizes, int n_in,
                              void* d_out, int out_size)
{
    const float* input_x = (const float*)d_in[0];
    const float* state_x = (const float*)d_in[1];
    const float* Ws      = (const float*)d_in[2];
    const float* bs      = (const float*)d_in[3];
    const float* We      = (const float*)d_in[4];
    const float* be      = (const float*)d_in[5];
    const float* tcv     = (const float*)d_in[6];
    const float* tsv     = (const float*)d_in[7];
    const float* tch     = (const float*)d_in[8];
    const float* tsh     = (const float*)d_in[9];
    const float* Wpv     = (const float*)d_in[10];
    const float* bpv     = (const float*)d_in[11];
    const float* Wph     = (const float*)d_in[12];
    const float* bph     = (const float*)d_in[13];
    const int*   rel_idx = (const int*)d_in[14];

    float* out   = (float*)d_out;
    float* state = out + (size_t)MTOK * CDIM;

    float *pXsT, *pXeT, *pWsT, *pWeT, *pWpvT, *pWphT, *pYs, *pYe, *pMvT, *pMhT;
    cudaGetSymbolAddress((void**)&pXsT,  g_XsT);
    cudaGetSymbolAddress((void**)&pXeT,  g_XeT);
    cudaGetSymbolAddress((void**)&pWsT,  g_WsT);
    cudaGetSymbolAddress((void**)&pWeT,  g_WeT);
    cudaGetSymbolAddress((void**)&pWpvT, g_WpvT);
    cudaGetSymbolAddress((void**)&pWphT, g_WphT);
    cudaGetSymbolAddress((void**)&pYs,   g_Ys);
    cudaGetSymbolAddress((void**)&pYe,   g_Ye);
    cudaGetSymbolAddress((void**)&pMvT,  g_MvT);
    cudaGetSymbolAddress((void**)&pMhT,  g_MhT);

    cudaFuncSetAttribute(attn_kernel,
                         cudaFuncAttributeMaxDynamicSharedMemorySize,
                         (int)ATTN_SMEM);

    // Pre-pass: transposes + bias gather (small)
    {
        dim3 gx(MTOK / 32, CDIM / 32);
        transpose_x<<<gx, 256>>>(state_x, pXsT);
        transpose_x<<<gx, 256>>>(input_x, pXeT);
        transpose_w<<<(K4 * CDIM + 255) / 256, 256>>>(Ws, pWsT, K4, CDIM);
        transpose_w<<<(K4 * CDIM + 255) / 256, 256>>>(We, pWeT, K4, CDIM);
        transpose_w<<<(CDIM * 2 * CDIM + 255) / 256, 256>>>(Wpv, pWpvT, CDIM, 2 * CDIM);
        transpose_w<<<(CDIM * 2 * CDIM + 255) / 256, 256>>>(Wph, pWphT, CDIM, 2 * CDIM);
        dim3 gb(NTOK * NTOK / 256, 4, NHEADS);
        bias_gather<<<gb, 256>>>(tcv, tsv, tch, tsh, rel_idx);
    }

    // Stage 1: projections  Y = X @ W^T + b   -> [M, 384]
    {
        dim3 grid(MTOK / BM, K4 / BN);      // (2048, 3)
        gemm_t<<<grid, 256>>>(pXsT, pWsT, bs, pYs, CDIM, K4);
        gemm_t<<<grid, 256>>>(pXeT, pWeT, be, pYe, CDIM, K4);
    }

    // Stage 2: 4 window attentions per (b, h) -> transposed merge buffers
    {
        dim3 grid(BATCH, NHEADS, 2);
        attn_kernel<<<grid, 128, ATTN_SMEM>>>();
    }

    // Stage 3: output projections (concat is free: K-halves of MvT/MhT)
    {
        dim3 grid(MTOK / BM, 1);
        gemm_t<<<grid, 256>>>(pMvT, pWpvT, bpv, out,   2 * CDIM, CDIM);
        gemm_t<<<grid, 256>>>(pMhT, pWphT, bph, state, 2 * CDIM, CDIM);
    }
}